// round 12
// baseline (speedup 1.0000x reference)
#include <cuda_runtime.h>
#include <cuda_fp16.h>
#include <stdint.h>
#include <math.h>

#define KSEL 2000
#define HH 75
#define WW 100
#define HWSZ 7500
#define NB 8
#define CH 512
#define ND 128
#define NROWS (NB * KSEL)
#define CPAIRS (CH / 2)     // 256
#define KPAD 2048
#define SST 20              // gemm2 smem row stride (words)

// gemm1 cp.async staging (word offsets within one stage)
#define ST_A 72                       // A row stride (64 m + 8 pad); 72%32==8 -> conflict-free frags
#define G1_AH 0
#define G1_AL (16 * ST_A)             // 1152
#define G1_BH (2 * 16 * ST_A)         // 2304
#define G1_BL (G1_BH + 128 * SST)     // 4864
#define G1_STGW (G1_BL + 128 * SST)   // 7424 words
#define G1_STGB (G1_STGW * 4)         // 29696 bytes
#define G1_SMEM (3 * G1_STGB)         // 89088

// ---------------- scratch (static device allocations) ----------------
__device__ int      g_sorted_idx[NROWS];
__device__ int      g_pos[NB * HWSZ];
__device__ int      g_addr[NB * KPAD];
__device__ unsigned g_nfh[(size_t)NB * CPAIRS * KPAD];  // A hi half2 [b][c2][k]
__device__ unsigned g_nfl[(size_t)NB * CPAIRS * KPAD];  // A lo half2
__device__ float    g_g1[NROWS * ND];
__device__ float    g_x1[NROWS * ND];
__device__ float    g_g2[NROWS * ND];
__device__ unsigned g_w1h[ND * (CH / 2)];               // [n][k2]
__device__ unsigned g_w1l[ND * (CH / 2)];
__device__ unsigned g_w2h[ND * (ND / 2)];
__device__ unsigned g_w2l[ND * (ND / 2)];

__device__ __forceinline__ unsigned desckey(float f) {
    unsigned u = __float_as_uint(f);
    unsigned ord = (u & 0x80000000u) ? ~u : (u ^ 0x80000000u);
    return ~ord;
}
__device__ __forceinline__ unsigned pack_split_hi(float v0, float v1) {
    __half h0 = __float2half_rn(v0), h1 = __float2half_rn(v1);
    return (unsigned)__half_as_ushort(h0) | ((unsigned)__half_as_ushort(h1) << 16);
}
__device__ __forceinline__ unsigned pack_split_lo(float v0, float v1) {
    __half h0 = __float2half_rn(v0), h1 = __float2half_rn(v1);
    __half l0 = __float2half_rn(v0 - __half2float(h0));
    __half l1 = __float2half_rn(v1 - __half2float(h1));
    return (unsigned)__half_as_ushort(l0) | ((unsigned)__half_as_ushort(l1) << 16);
}
__device__ __forceinline__ uint32_t s2u(const void* p) {
    return (uint32_t)__cvta_generic_to_shared(p);
}

#define CP16(dst, src) \
    asm volatile("cp.async.cg.shared.global [%0], [%1], 16;" \
                 :: "r"(dst), "l"(src) : "memory")

// ---------------- weight split prep ----------------
extern "C" __global__ __launch_bounds__(256)
void prep_kernel(const float* __restrict__ w1, const float* __restrict__ w2) {
    int idx = blockIdx.x * 256 + threadIdx.x;
    const int N1 = ND * (CH / 2);
    if (idx < N1) {
        int f = idx % ND, c2 = idx / ND;
        float v0 = w1[(2 * c2) * ND + f], v1 = w1[(2 * c2 + 1) * ND + f];
        g_w1h[f * (CH / 2) + c2] = pack_split_hi(v0, v1);
        g_w1l[f * (CH / 2) + c2] = pack_split_lo(v0, v1);
    } else {
        int j = idx - N1;
        if (j < ND * (ND / 2)) {
            int f = j % ND, c2 = j / ND;
            float v0 = w2[(2 * c2) * ND + f], v1 = w2[(2 * c2 + 1) * ND + f];
            g_w2h[f * (ND / 2) + c2] = pack_split_hi(v0, v1);
            g_w2l[f * (ND / 2) + c2] = pack_split_lo(v0, v1);
        }
    }
}

// ---------------- kernel 1: per-batch exact top-K via radix histogram ----------------
extern "C" __global__ __launch_bounds__(1024)
void topk_kernel(const float* __restrict__ predict, float* __restrict__ out, int write_idx) {
    __shared__ int hist[2048];
    __shared__ int partial[64];
    __shared__ unsigned long long cand[2048];
    __shared__ unsigned char flag[HWSZ];
    __shared__ int scanbuf[1024];
    __shared__ int s_bin, s_before, s_cnt;

    const int b = blockIdx.x;
    const int tid = threadIdx.x;
    const float* sc = predict + (size_t)b * 3 * HWSZ;

    for (int i = tid; i < 2048; i += 1024) hist[i] = 0;
    for (int i = tid; i < HWSZ; i += 1024) { flag[i] = 0; g_pos[b * HWSZ + i] = -1; }
    if (tid < KPAD - KSEL) g_addr[b * KPAD + KSEL + tid] = -1;
    if (tid == 0) s_cnt = 0;
    __syncthreads();

    for (int i = tid; i < HWSZ; i += 1024)
        atomicAdd(&hist[desckey(sc[i]) >> 21], 1);
    __syncthreads();

    if (tid < 64) {
        int s = 0;
        #pragma unroll
        for (int j = 0; j < 32; j++) s += hist[tid * 32 + j];
        partial[tid] = s;
    }
    __syncthreads();
    if (tid == 0) {
        int run = 0;
        for (int t = 0; t < 64; t++) { int v = partial[t]; partial[t] = run; run += v; }
    }
    __syncthreads();
    if (tid < 64) {
        int run = partial[tid];
        #pragma unroll
        for (int j = 0; j < 32; j++) { run += hist[tid * 32 + j]; hist[tid * 32 + j] = run; }
    }
    __syncthreads();

    for (int bin = tid; bin < 2048; bin += 1024) {
        int c = hist[bin];
        int cb = (bin == 0) ? 0 : hist[bin - 1];
        if (c >= KSEL && cb < KSEL) { s_bin = bin; s_before = cb; }
    }
    __syncthreads();
    const int Bb = s_bin;
    const int r = KSEL - s_before;

    for (int i = tid; i < HWSZ; i += 1024) {
        unsigned k = desckey(sc[i]);
        if ((int)(k >> 21) == Bb) {
            int slot = atomicAdd(&s_cnt, 1);
            if (slot < 2048) cand[slot] = (((unsigned long long)k) << 32) | (unsigned)i;
        }
    }
    __syncthreads();
    int cnt = s_cnt; if (cnt > 2048) cnt = 2048;

    if (r >= cnt) {
        for (int j = tid; j < cnt; j += 1024)
            flag[(int)(cand[j] & 0xFFFFFFFFu)] = 1;
    } else {
        int S = 2; while (S < cnt) S <<= 1;
        for (int i = tid; i < S; i += 1024)
            if (i >= cnt) cand[i] = 0xFFFFFFFFFFFFFFFFULL;
        __syncthreads();
        for (int size = 2; size <= S; size <<= 1) {
            for (int stride = size >> 1; stride > 0; stride >>= 1) {
                for (int i = tid; i < S; i += 1024) {
                    int j = i ^ stride;
                    if (j > i) {
                        unsigned long long a = cand[i], c = cand[j];
                        bool up = ((i & size) == 0);
                        if ((a > c) == up) { cand[i] = c; cand[j] = a; }
                    }
                }
                __syncthreads();
            }
        }
        for (int j = tid; j < r; j += 1024)
            flag[(int)(cand[j] & 0xFFFFFFFFu)] = 1;
    }
    __syncthreads();

    const int lo = tid * 8;
    int mycnt = 0;
    #pragma unroll
    for (int q = 0; q < 8; q++) {
        int i = lo + q;
        if (i < HWSZ) {
            int bin = desckey(sc[i]) >> 21;
            if (bin < Bb || flag[i]) mycnt++;
        }
    }
    scanbuf[tid] = mycnt;
    __syncthreads();
    for (int off = 1; off < 1024; off <<= 1) {
        int v = (tid >= off) ? scanbuf[tid - off] : 0;
        __syncthreads();
        scanbuf[tid] += v;
        __syncthreads();
    }
    int pos = scanbuf[tid] - mycnt;
    #pragma unroll
    for (int q = 0; q < 8; q++) {
        int i = lo + q;
        if (i < HWSZ) {
            int bin = desckey(sc[i]) >> 21;
            if (bin < Bb || flag[i]) {
                g_sorted_idx[b * KSEL + pos] = i;
                g_pos[b * HWSZ + i] = pos;
                g_addr[b * KPAD + pos] = (i % HH) * WW + i / HH;
                if (write_idx) out[(size_t)NROWS * ND + b * KSEL + pos] = (float)i;
                pos++;
            }
        }
    }
}

// ---------------- kernel 2: bulk-copy gather + clip + fp16 split ----------------
extern "C" __global__ __launch_bounds__(256)
void gather_kernel(const float* __restrict__ feat) {
    extern __shared__ float sp[];
    __shared__ __align__(8) unsigned long long mbar;
    const int blk = blockIdx.x;
    const int b = blk >> 8, c2 = blk & 255;
    const int tid = threadIdx.x;
    const uint32_t mb = s2u(&mbar);

    if (tid == 0)
        asm volatile("mbarrier.init.shared.b64 [%0], %1;" :: "r"(mb), "r"(1) : "memory");
    __syncthreads();
    if (tid == 0) {
        asm volatile("mbarrier.arrive.expect_tx.shared.b64 _, [%0], %1;"
                     :: "r"(mb), "r"(60000) : "memory");
        const float* src = feat + ((size_t)b * CH + 2 * c2) * HWSZ;
        uint32_t d0 = s2u(sp);
        asm volatile("cp.async.bulk.shared::cluster.global.mbarrier::complete_tx::bytes "
                     "[%0], [%1], %2, [%3];"
                     :: "r"(d0), "l"(src), "r"(30000), "r"(mb) : "memory");
        asm volatile("cp.async.bulk.shared::cluster.global.mbarrier::complete_tx::bytes "
                     "[%0], [%1], %2, [%3];"
                     :: "r"(d0 + 30000), "l"(src + HWSZ), "r"(30000), "r"(mb) : "memory");
    }
    asm volatile(
        "{\n\t.reg .pred P;\n"
        "LW%=:\n\t mbarrier.try_wait.parity.acquire.cta.shared::cta.b64 P, [%0], %1;\n"
        "\t@P bra LD%=;\n\t bra LW%=;\n"
        "LD%=:\n\t}" :: "r"(mb), "r"(0) : "memory");

    const int kb = b * KPAD;
    const size_t oh = ((size_t)b * CPAIRS + c2) * KPAD;
    #pragma unroll
    for (int q = 0; q < 2; q++) {
        int k0 = tid * 8 + q * 4;
        unsigned h[4], l[4];
        #pragma unroll
        for (int j = 0; j < 4; j++) {
            int a = g_addr[kb + k0 + j];
            float v0 = 0.0f, v1 = 0.0f;
            if (a >= 0) {
                v0 = fminf(fmaxf(sp[a], 0.0f), 6.0f);
                v1 = fminf(fmaxf(sp[HWSZ + a], 0.0f), 6.0f);
            }
            h[j] = pack_split_hi(v0, v1);
            l[j] = pack_split_lo(v0, v1);
        }
        *(uint4*)&g_nfh[oh + k0] = make_uint4(h[0], h[1], h[2], h[3]);
        *(uint4*)&g_nfl[oh + k0] = make_uint4(l[0], l[1], l[2], l[3]);
    }
}

// ---------------- MMA / ldmatrix helpers ----------------
#define MMA_F16(acc, a0, a1, a2, a3, b0, b1)                                    \
    asm volatile(                                                               \
        "mma.sync.aligned.m16n8k16.row.col.f32.f16.f16.f32 "                    \
        "{%0,%1,%2,%3}, {%4,%5,%6,%7}, {%8,%9}, {%0,%1,%2,%3};"                 \
        : "+f"(acc[0]), "+f"(acc[1]), "+f"(acc[2]), "+f"(acc[3])                \
        : "r"(a0), "r"(a1), "r"(a2), "r"(a3), "r"(b0), "r"(b1))

#define LDSM_X4(r0, r1, r2, r3, addr)                                           \
    asm volatile("ldmatrix.sync.aligned.m8n8.x4.shared.b16 {%0,%1,%2,%3}, [%4];"\
        : "=r"(r0), "=r"(r1), "=r"(r2), "=r"(r3) : "r"(addr))

// ---------------- gemm1: g1 = nf @ w1 — cp.async 3-stage, A k-major ----------------
extern "C" __global__ __launch_bounds__(256, 2)
void gemm1_kernel() {
    extern __shared__ unsigned dsm[];              // 3 * G1_STGW words
    const int tid  = threadIdx.x;
    const int lane = tid & 31;
    const int warp = tid >> 5;
    const int wm = (warp & 1) * 32;                // 2 m-warps
    const int wn = (warp >> 1) * 32;               // 4 n-warps
    const int b = blockIdx.x >> 5;                 // batch
    const int t = blockIdx.x & 31;                 // M64 tile

    // cp.async thread mapping
    const int ac2 = tid >> 4;                      // 0..15 (c2 within k-tile)
    const int am4 = (tid & 15) * 4;                // m quad
    const int bn  = tid >> 1;                      // 0..127
    const int bk8 = (tid & 1) * 8;

    const size_t abase = (size_t)b * CPAIRS * KPAD + t * 64;
    const uint32_t sbase = s2u(dsm);

    float acc[2][4][4];
    #pragma unroll
    for (int mt = 0; mt < 2; mt++)
        #pragma unroll
        for (int nt = 0; nt < 4; nt++)
            #pragma unroll
            for (int q = 0; q < 4; q++) acc[mt][nt][q] = 0.0f;

    // A fragment word offsets (within stage): a0 at (c2=ks*8+(lane&3), m=wm+mt*16+(lane>>2))
    int aw[2];
    #pragma unroll
    for (int mt = 0; mt < 2; mt++)
        aw[mt] = (lane & 3) * ST_A + wm + mt * 16 + (lane >> 2);

    // B ldmatrix byte addresses (stage 0)
    uint32_t bA0[2];
    #pragma unroll
    for (int p = 0; p < 2; p++) {
        int row = wn + p * 16 + ((lane >> 4) << 3) + (lane & 7);
        int col = ((lane >> 3) & 1) * 4;
        bA0[p] = sbase + (uint32_t)(G1_BH + row * SST + col) * 4;
    }

    // stage issue: 6 x 16B cp.async per thread
    auto issue_stage = [&](int kt, int stg) {
        const uint32_t sw = sbase + (uint32_t)(stg * G1_STGW) * 4;
        const size_t ga = abase + (size_t)(kt * 16 + ac2) * KPAD + am4;
        CP16(sw + (uint32_t)(G1_AH + ac2 * ST_A + am4) * 4, &g_nfh[ga]);
        CP16(sw + (uint32_t)(G1_AL + ac2 * ST_A + am4) * 4, &g_nfl[ga]);
        const int gb = bn * (CH / 2) + kt * 16 + bk8;
        CP16(sw + (uint32_t)(G1_BH + bn * SST + bk8) * 4,     &g_w1h[gb]);
        CP16(sw + (uint32_t)(G1_BH + bn * SST + bk8 + 4) * 4, &g_w1h[gb + 4]);
        CP16(sw + (uint32_t)(G1_BL + bn * SST + bk8) * 4,     &g_w1l[gb]);
        CP16(sw + (uint32_t)(G1_BL + bn * SST + bk8 + 4) * 4, &g_w1l[gb + 4]);
        asm volatile("cp.async.commit_group;" ::: "memory");
    };

    issue_stage(0, 0);
    issue_stage(1, 1);
    issue_stage(2, 2);

    for (int kt = 0; kt < 16; kt++) {
        const int stg = kt % 3;
        if (kt < 14)       asm volatile("cp.async.wait_group 2;" ::: "memory");
        else if (kt == 14) asm volatile("cp.async.wait_group 1;" ::: "memory");
        else               asm volatile("cp.async.wait_group 0;" ::: "memory");
        __syncthreads();

        const int sbw = stg * G1_STGW;
        const uint32_t sbb = (uint32_t)(stg * G1_STGW) * 4;

        #pragma unroll
        for (int ks = 0; ks < 2; ks++) {
            const int ko = ks * 8 * ST_A;
            unsigned aH[2][4], aL[2][4], bHf[4][2], bLf[4][2];
            #pragma unroll
            for (int mt = 0; mt < 2; mt++) {
                int base = sbw + aw[mt] + ko;
                aH[mt][0] = dsm[base];
                aH[mt][1] = dsm[base + 8];
                aH[mt][2] = dsm[base + 4 * ST_A];
                aH[mt][3] = dsm[base + 4 * ST_A + 8];
                aL[mt][0] = dsm[base + G1_AL];
                aL[mt][1] = dsm[base + G1_AL + 8];
                aL[mt][2] = dsm[base + G1_AL + 4 * ST_A];
                aL[mt][3] = dsm[base + G1_AL + 4 * ST_A + 8];
            }
            #pragma unroll
            for (int p = 0; p < 2; p++) {
                LDSM_X4(bHf[2*p][0], bHf[2*p][1], bHf[2*p+1][0], bHf[2*p+1][1],
                        bA0[p] + sbb + ks * 32);
                LDSM_X4(bLf[2*p][0], bLf[2*p][1], bLf[2*p+1][0], bLf[2*p+1][1],
                        bA0[p] + sbb + ks * 32 + (uint32_t)(G1_BL - G1_BH) * 4);
            }
            #pragma unroll
            for (int mt = 0; mt < 2; mt++)
                #pragma unroll
                for (int nt = 0; nt < 4; nt++) {
                    MMA_F16(acc[mt][nt], aL[mt][0], aL[mt][1], aL[mt][2], aL[mt][3],
                            bHf[nt][0], bHf[nt][1]);
                    MMA_F16(acc[mt][nt], aH[mt][0], aH[mt][1], aH[mt][2], aH[mt][3],
                            bLf[nt][0], bLf[nt][1]);
                    MMA_F16(acc[mt][nt], aH[mt][0], aH[mt][1], aH[mt][2], aH[mt][3],
                            bHf[nt][0], bHf[nt][1]);
                }
        }
        __syncthreads();                   // all reads of stage done before refill
        if (kt + 3 < 16) issue_stage(kt + 3, stg);
    }

    #pragma unroll
    for (int mt = 0; mt < 2; mt++) {
        int rk = t * 64 + wm + mt * 16 + (lane >> 2);
        int colb = (lane & 3) * 2;
        #pragma unroll
        for (int nt = 0; nt < 4; nt++) {
            int col = wn + nt * 8 + colb;
            if (rk < KSEL)
                *(float2*)&g_g1[(size_t)(b * KSEL + rk) * ND + col] =
                    make_float2(acc[mt][nt][0], acc[mt][nt][1]);
            if (rk + 8 < KSEL)
                *(float2*)&g_g1[(size_t)(b * KSEL + rk + 8) * ND + col] =
                    make_float2(acc[mt][nt][2], acc[mt][nt][3]);
        }
    }
}

// ---------------- gemm2: g2 = x1 @ w2 (unchanged from R10) ----------------
struct GemmSmem {
    unsigned AsH[64 * SST], AsL[64 * SST];
    unsigned BsH[128 * SST], BsL[128 * SST];
};

extern "C" __global__ __launch_bounds__(256, 2)
void gemm2_kernel() {
    __shared__ GemmSmem S;
    const int tid  = threadIdx.x;
    const int lane = tid & 31;
    const int warp = tid >> 5;
    const int wm = (warp & 1) * 32;
    const int wn = (warp >> 1) * 32;
    const int gm = blockIdx.x * 64;
    const int K2 = ND / 2;

    const int arow = tid >> 2, aq = tid & 3;
    const int brow = tid >> 1, bkb = (tid & 1) * 8;

    float acc[2][4][4];
    #pragma unroll
    for (int mt = 0; mt < 2; mt++)
        #pragma unroll
        for (int nt = 0; nt < 4; nt++)
            #pragma unroll
            for (int q = 0; q < 4; q++) acc[mt][nt][q] = 0.0f;

    uint32_t aAH[2], aAL[2], bAH[2], bAL[2];
    #pragma unroll
    for (int mt = 0; mt < 2; mt++) {
        int row = wm + mt * 16 + (lane & 15);
        int col = (lane >> 4) << 2;
        aAH[mt] = s2u(&S.AsH[row * SST + col]);
        aAL[mt] = s2u(&S.AsL[row * SST + col]);
    }
    #pragma unroll
    for (int p = 0; p < 2; p++) {
        int row = wn + p * 16 + ((lane >> 4) << 3) + (lane & 7);
        int col = ((lane >> 3) & 1) * 4;
        bAH[p] = s2u(&S.BsH[row * SST + col]);
        bAL[p] = s2u(&S.BsL[row * SST + col]);
    }

    float v[8];
    uint4 bh[2], bl[2];
    {
        #pragma unroll
        for (int q = 0; q < 2; q++) {
            float4 tv = *(const float4*)&g_x1[(size_t)(gm + arow) * ND + aq * 8 + q * 4];
            v[q * 4] = tv.x; v[q * 4 + 1] = tv.y; v[q * 4 + 2] = tv.z; v[q * 4 + 3] = tv.w;
        }
        bh[0] = *(const uint4*)&g_w2h[brow * K2 + bkb];
        bh[1] = *(const uint4*)&g_w2h[brow * K2 + bkb + 4];
        bl[0] = *(const uint4*)&g_w2l[brow * K2 + bkb];
        bl[1] = *(const uint4*)&g_w2l[brow * K2 + bkb + 4];
    }

    for (int kt = 0; kt < 4; kt++) {
        __syncthreads();
        #pragma unroll
        for (int j = 0; j < 4; j++) {
            int kidx = arow * SST + aq * 4 + j;
            S.AsH[kidx] = pack_split_hi(v[2 * j], v[2 * j + 1]);
            S.AsL[kidx] = pack_split_lo(v[2 * j], v[2 * j + 1]);
        }
        {
            int base = brow * SST + bkb;
            S.BsH[base + 0] = bh[0].x; S.BsH[base + 1] = bh[0].y;
            S.BsH[base + 2] = bh[0].z; S.BsH[base + 3] = bh[0].w;
            S.BsH[base + 4] = bh[1].x; S.BsH[base + 5] = bh[1].y;
            S.BsH[base + 6] = bh[1].z; S.BsH[base + 7] = bh[1].w;
            S.BsL[base + 0] = bl[0].x; S.BsL[base + 1] = bl[0].y;
            S.BsL[base + 2] = bl[0].z; S.BsL[base + 3] = bl[0].w;
            S.BsL[base + 4] = bl[1].x; S.BsL[base + 5] = bl[1].y;
            S.BsL[base + 6] = bl[1].z; S.BsL[base + 7] = bl[1].w;
        }
        __syncthreads();

        if (kt + 1 < 4) {
            int cb = (kt + 1) * 32 + aq * 8;
            #pragma unroll
            for (int q = 0; q < 2; q++) {
                float4 tv = *(const float4*)&g_x1[(size_t)(gm + arow) * ND + cb + q * 4];
                v[q * 4] = tv.x; v[q * 4 + 1] = tv.y; v[q * 4 + 2] = tv.z; v[q * 4 + 3] = tv.w;
            }
            int k2n = (kt + 1) * 16;
            bh[0] = *(const uint4*)&g_w2h[brow * K2 + k2n + bkb];
            bh[1] = *(const uint4*)&g_w2h[brow * K2 + k2n + bkb + 4];
            bl[0] = *(const uint4*)&g_w2l[brow * K2 + k2n + bkb];
            bl[1] = *(const uint4*)&g_w2l[brow * K2 + k2n + bkb + 4];
        }

        #pragma unroll
        for (int ks = 0; ks < 2; ks++) {
            const uint32_t off = ks * 32;
            unsigned aH[2][4], aL[2][4], bHf[4][2], bLf[4][2];
            #pragma unroll
            for (int mt = 0; mt < 2; mt++) {
                LDSM_X4(aH[mt][0], aH[mt][1], aH[mt][2], aH[mt][3], aAH[mt] + off);
                LDSM_X4(aL[mt][0], aL[mt][1], aL[mt][2], aL[mt][3], aAL[mt] + off);
            }
            #pragma unroll
            for (int p = 0; p < 2; p++) {
                LDSM_X4(bHf[2*p][0], bHf[2*p][1], bHf[2*p+1][0], bHf[2*p+1][1], bAH[p] + off);
                LDSM_X4(bLf[2*p][0], bLf[2*p][1], bLf[2*p+1][0], bLf[2*p+1][1], bAL[p] + off);
            }
            #pragma unroll
            for (int mt = 0; mt < 2; mt++)
                #pragma unroll
                for (int nt = 0; nt < 4; nt++) {
                    MMA_F16(acc[mt][nt], aL[mt][0], aL[mt][1], aL[mt][2], aL[mt][3],
                            bHf[nt][0], bHf[nt][1]);
                    MMA_F16(acc[mt][nt], aH[mt][0], aH[mt][1], aH[mt][2], aH[mt][3],
                            bLf[nt][0], bLf[nt][1]);
                    MMA_F16(acc[mt][nt], aH[mt][0], aH[mt][1], aH[mt][2], aH[mt][3],
                            bHf[nt][0], bHf[nt][1]);
                }
        }
    }

    #pragma unroll
    for (int mt = 0; mt < 2; mt++) {
        int row0 = gm + wm + mt * 16 + (lane >> 2);
        int colb = (lane & 3) * 2;
        #pragma unroll
        for (int nt = 0; nt < 4; nt++) {
            int col = wn + nt * 8 + colb;
            *(float2*)&g_g2[(size_t)row0 * ND + col] =
                make_float2(acc[mt][nt][0], acc[mt][nt][1]);
            *(float2*)&g_g2[(size_t)(row0 + 8) * ND + col] =
                make_float2(acc[mt][nt][2], acc[mt][nt][3]);
        }
    }
}

// ---------------- sparse 3x3 neighbor sums ----------------
extern "C" __global__ __launch_bounds__(256)
void nsum1_kernel(const float* __restrict__ b1) {
    const int row = blockIdx.x * 8 + (threadIdx.x >> 5);
    const int lane = threadIdx.x & 31;
    const int b = row / KSEL, k = row - b * KSEL;
    const int i = g_sorted_idx[row];
    const int py = i / WW, px = i % WW;
    int nb = -1;
    if (lane < 9) {
        int ny = py + lane / 3 - 1, nx = px + lane % 3 - 1;
        if ((unsigned)ny < HH && (unsigned)nx < WW)
            nb = g_pos[b * HWSZ + ny * WW + nx];
    }
    float4 acc = *(const float4*)&b1[(size_t)k * ND + lane * 4];
    #pragma unroll
    for (int j = 0; j < 9; j++) {
        int n = __shfl_sync(0xFFFFFFFFu, nb, j);
        if (n >= 0) {
            float4 v = *(const float4*)&g_g1[(size_t)(b * KSEL + n) * ND + lane * 4];
            acc.x += v.x; acc.y += v.y; acc.z += v.z; acc.w += v.w;
        }
    }
    *(float4*)&g_x1[(size_t)row * ND + lane * 4] = acc;
}

extern "C" __global__ __launch_bounds__(256)
void final_kernel(const float* __restrict__ b2, float* __restrict__ out) {
    const int row = blockIdx.x * 8 + (threadIdx.x >> 5);
    const int lane = threadIdx.x & 31;
    const int b = row / KSEL, k = row - b * KSEL;
    const int i = g_sorted_idx[row];
    const int py = i / WW, px = i % WW;
    int nb = -1;
    if (lane < 9) {
        int ny = py + lane / 3 - 1, nx = px + lane % 3 - 1;
        if ((unsigned)ny < HH && (unsigned)nx < WW)
            nb = g_pos[b * HWSZ + ny * WW + nx];
    }
    float4 acc = *(const float4*)&b2[(size_t)k * ND + lane * 4];
    float4 x1v = *(const float4*)&g_x1[(size_t)row * ND + lane * 4];
    acc.x += x1v.x; acc.y += x1v.y; acc.z += x1v.z; acc.w += x1v.w;
    #pragma unroll
    for (int j = 0; j < 9; j++) {
        int n = __shfl_sync(0xFFFFFFFFu, nb, j);
        if (n >= 0) {
            float4 v = *(const float4*)&g_g2[(size_t)(b * KSEL + n) * ND + lane * 4];
            acc.x += v.x; acc.y += v.y; acc.z += v.z; acc.w += v.w;
        }
    }
    float4 o = make_float4(tanhf(acc.x), tanhf(acc.y), tanhf(acc.z), tanhf(acc.w));
    *(float4*)&out[(size_t)row * ND + lane * 4] = o;
}

// ---------------- launch ----------------
extern "C" void kernel_launch(void* const* d_in, const int* in_sizes, int n_in,
                              void* d_out, int out_size) {
    const float* feat = (const float*)d_in[0];
    const float* pred = (const float*)d_in[1];
    const float* w1   = (const float*)d_in[2];
    const float* b1   = (const float*)d_in[3];
    const float* w2   = (const float*)d_in[4];
    const float* b2   = (const float*)d_in[5];
    float* out = (float*)d_out;

    const int feat_elems = NROWS * ND;
    const int write_idx = (out_size >= feat_elems + NROWS) ? 1 : 0;

    cudaFuncSetAttribute((const void*)gather_kernel,
                         cudaFuncAttributeMaxDynamicSharedMemorySize, 60000);
    cudaFuncSetAttribute((const void*)gemm1_kernel,
                         cudaFuncAttributeMaxDynamicSharedMemorySize, G1_SMEM);

    prep_kernel<<<(ND * (CH / 2) + ND * (ND / 2) + 255) / 256, 256>>>(w1, w2);
    topk_kernel<<<NB, 1024>>>(pred, out, write_idx);
    gather_kernel<<<NB * CPAIRS, 256, 60000>>>(feat);
    gemm1_kernel<<<NB * 32, 256, G1_SMEM>>>();
    nsum1_kernel<<<NROWS / 8, 256>>>(b1);
    gemm2_kernel<<<NROWS / 64, 256>>>();
    final_kernel<<<NROWS / 8, 256>>>(b2, out);
}

// round 13
// speedup vs baseline: 1.0204x; 1.0204x over previous
#include <cuda_runtime.h>
#include <cuda_fp16.h>
#include <stdint.h>
#include <math.h>

#define KSEL 2000
#define HH 75
#define WW 100
#define HWSZ 7500
#define NB 8
#define CH 512
#define ND 128
#define NROWS (NB * KSEL)
#define CPAIRS (CH / 2)     // 256
#define KPAD 2048
#define SST 20              // gemm2 smem row stride (words)

// gemm1 cp.async staging (word offsets within one stage)
#define ST_A 72
#define G1_AH 0
#define G1_AL (16 * ST_A)
#define G1_BH (2 * 16 * ST_A)
#define G1_BL (G1_BH + 128 * SST)
#define G1_STGW (G1_BL + 128 * SST)
#define G1_STGB (G1_STGW * 4)
#define G1_SMEM (3 * G1_STGB)

// ---------------- scratch (static device allocations) ----------------
__device__ int      g_sorted_idx[NROWS];
__device__ int      g_pos[NB * HWSZ];
__device__ int      g_addr[NB * KPAD];
__device__ unsigned g_nfh[(size_t)NB * CPAIRS * KPAD];
__device__ unsigned g_nfl[(size_t)NB * CPAIRS * KPAD];
__device__ float    g_g1[NROWS * ND];
__device__ float    g_x1[NROWS * ND];
__device__ float    g_g2[NROWS * ND];
__device__ unsigned g_w1h[ND * (CH / 2)];
__device__ unsigned g_w1l[ND * (CH / 2)];
__device__ unsigned g_w2h[ND * (ND / 2)];
__device__ unsigned g_w2l[ND * (ND / 2)];

__device__ __forceinline__ unsigned desckey(float f) {
    unsigned u = __float_as_uint(f);
    unsigned ord = (u & 0x80000000u) ? ~u : (u ^ 0x80000000u);
    return ~ord;
}
__device__ __forceinline__ unsigned pack_split_hi(float v0, float v1) {
    __half h0 = __float2half_rn(v0), h1 = __float2half_rn(v1);
    return (unsigned)__half_as_ushort(h0) | ((unsigned)__half_as_ushort(h1) << 16);
}
__device__ __forceinline__ unsigned pack_split_lo(float v0, float v1) {
    __half h0 = __float2half_rn(v0), h1 = __float2half_rn(v1);
    __half l0 = __float2half_rn(v0 - __half2float(h0));
    __half l1 = __float2half_rn(v1 - __half2float(h1));
    return (unsigned)__half_as_ushort(l0) | ((unsigned)__half_as_ushort(l1) << 16);
}
__device__ __forceinline__ uint32_t s2u(const void* p) {
    return (uint32_t)__cvta_generic_to_shared(p);
}

#define CP16(dst, src) \
    asm volatile("cp.async.cg.shared.global [%0], [%1], 16;" \
                 :: "r"(dst), "l"(src) : "memory")

// ---------------- weight split prep ----------------
extern "C" __global__ __launch_bounds__(256)
void prep_kernel(const float* __restrict__ w1, const float* __restrict__ w2) {
    int idx = blockIdx.x * 256 + threadIdx.x;
    const int N1 = ND * (CH / 2);
    if (idx < N1) {
        int f = idx % ND, c2 = idx / ND;
        float v0 = w1[(2 * c2) * ND + f], v1 = w1[(2 * c2 + 1) * ND + f];
        g_w1h[f * (CH / 2) + c2] = pack_split_hi(v0, v1);
        g_w1l[f * (CH / 2) + c2] = pack_split_lo(v0, v1);
    } else {
        int j = idx - N1;
        if (j < ND * (ND / 2)) {
            int f = j % ND, c2 = j / ND;
            float v0 = w2[(2 * c2) * ND + f], v1 = w2[(2 * c2 + 1) * ND + f];
            g_w2h[f * (ND / 2) + c2] = pack_split_hi(v0, v1);
            g_w2l[f * (ND / 2) + c2] = pack_split_lo(v0, v1);
        }
    }
}

// ---------------- kernel 1: per-batch exact top-K via radix histogram ----------------
extern "C" __global__ __launch_bounds__(1024)
void topk_kernel(const float* __restrict__ predict, float* __restrict__ out, int write_idx) {
    __shared__ int hist[2048];
    __shared__ int partial[64];
    __shared__ unsigned long long cand[2048];
    __shared__ unsigned char flag[HWSZ];
    __shared__ int scanbuf[1024];
    __shared__ int s_bin, s_before, s_cnt;

    const int b = blockIdx.x;
    const int tid = threadIdx.x;
    const float* sc = predict + (size_t)b * 3 * HWSZ;

    for (int i = tid; i < 2048; i += 1024) hist[i] = 0;
    for (int i = tid; i < HWSZ; i += 1024) { flag[i] = 0; g_pos[b * HWSZ + i] = -1; }
    if (tid < KPAD - KSEL) g_addr[b * KPAD + KSEL + tid] = -1;
    if (tid == 0) s_cnt = 0;
    __syncthreads();

    for (int i = tid; i < HWSZ; i += 1024)
        atomicAdd(&hist[desckey(sc[i]) >> 21], 1);
    __syncthreads();

    if (tid < 64) {
        int s = 0;
        #pragma unroll
        for (int j = 0; j < 32; j++) s += hist[tid * 32 + j];
        partial[tid] = s;
    }
    __syncthreads();
    if (tid == 0) {
        int run = 0;
        for (int t = 0; t < 64; t++) { int v = partial[t]; partial[t] = run; run += v; }
    }
    __syncthreads();
    if (tid < 64) {
        int run = partial[tid];
        #pragma unroll
        for (int j = 0; j < 32; j++) { run += hist[tid * 32 + j]; hist[tid * 32 + j] = run; }
    }
    __syncthreads();

    for (int bin = tid; bin < 2048; bin += 1024) {
        int c = hist[bin];
        int cb = (bin == 0) ? 0 : hist[bin - 1];
        if (c >= KSEL && cb < KSEL) { s_bin = bin; s_before = cb; }
    }
    __syncthreads();
    const int Bb = s_bin;
    const int r = KSEL - s_before;

    for (int i = tid; i < HWSZ; i += 1024) {
        unsigned k = desckey(sc[i]);
        if ((int)(k >> 21) == Bb) {
            int slot = atomicAdd(&s_cnt, 1);
            if (slot < 2048) cand[slot] = (((unsigned long long)k) << 32) | (unsigned)i;
        }
    }
    __syncthreads();
    int cnt = s_cnt; if (cnt > 2048) cnt = 2048;

    if (r >= cnt) {
        for (int j = tid; j < cnt; j += 1024)
            flag[(int)(cand[j] & 0xFFFFFFFFu)] = 1;
    } else {
        int S = 2; while (S < cnt) S <<= 1;
        for (int i = tid; i < S; i += 1024)
            if (i >= cnt) cand[i] = 0xFFFFFFFFFFFFFFFFULL;
        __syncthreads();
        for (int size = 2; size <= S; size <<= 1) {
            for (int stride = size >> 1; stride > 0; stride >>= 1) {
                for (int i = tid; i < S; i += 1024) {
                    int j = i ^ stride;
                    if (j > i) {
                        unsigned long long a = cand[i], c = cand[j];
                        bool up = ((i & size) == 0);
                        if ((a > c) == up) { cand[i] = c; cand[j] = a; }
                    }
                }
                __syncthreads();
            }
        }
        for (int j = tid; j < r; j += 1024)
            flag[(int)(cand[j] & 0xFFFFFFFFu)] = 1;
    }
    __syncthreads();

    const int lo = tid * 8;
    int mycnt = 0;
    #pragma unroll
    for (int q = 0; q < 8; q++) {
        int i = lo + q;
        if (i < HWSZ) {
            int bin = desckey(sc[i]) >> 21;
            if (bin < Bb || flag[i]) mycnt++;
        }
    }
    scanbuf[tid] = mycnt;
    __syncthreads();
    for (int off = 1; off < 1024; off <<= 1) {
        int v = (tid >= off) ? scanbuf[tid - off] : 0;
        __syncthreads();
        scanbuf[tid] += v;
        __syncthreads();
    }
    int pos = scanbuf[tid] - mycnt;
    #pragma unroll
    for (int q = 0; q < 8; q++) {
        int i = lo + q;
        if (i < HWSZ) {
            int bin = desckey(sc[i]) >> 21;
            if (bin < Bb || flag[i]) {
                g_sorted_idx[b * KSEL + pos] = i;
                g_pos[b * HWSZ + i] = pos;
                g_addr[b * KPAD + pos] = (i % HH) * WW + i / HH;
                if (write_idx) out[(size_t)NROWS * ND + b * KSEL + pos] = (float)i;
                pos++;
            }
        }
    }
}

// ---------------- kernel 2: bulk-copy gather + clip + fp16 split ----------------
extern "C" __global__ __launch_bounds__(256)
void gather_kernel(const float* __restrict__ feat) {
    extern __shared__ float sp[];
    __shared__ __align__(8) unsigned long long mbar;
    const int blk = blockIdx.x;
    const int b = blk >> 8, c2 = blk & 255;
    const int tid = threadIdx.x;
    const uint32_t mb = s2u(&mbar);

    if (tid == 0)
        asm volatile("mbarrier.init.shared.b64 [%0], %1;" :: "r"(mb), "r"(1) : "memory");
    __syncthreads();
    if (tid == 0) {
        asm volatile("mbarrier.arrive.expect_tx.shared.b64 _, [%0], %1;"
                     :: "r"(mb), "r"(60000) : "memory");
        const float* src = feat + ((size_t)b * CH + 2 * c2) * HWSZ;
        uint32_t d0 = s2u(sp);
        asm volatile("cp.async.bulk.shared::cluster.global.mbarrier::complete_tx::bytes "
                     "[%0], [%1], %2, [%3];"
                     :: "r"(d0), "l"(src), "r"(30000), "r"(mb) : "memory");
        asm volatile("cp.async.bulk.shared::cluster.global.mbarrier::complete_tx::bytes "
                     "[%0], [%1], %2, [%3];"
                     :: "r"(d0 + 30000), "l"(src + HWSZ), "r"(30000), "r"(mb) : "memory");
    }
    asm volatile(
        "{\n\t.reg .pred P;\n"
        "LW%=:\n\t mbarrier.try_wait.parity.acquire.cta.shared::cta.b64 P, [%0], %1;\n"
        "\t@P bra LD%=;\n\t bra LW%=;\n"
        "LD%=:\n\t}" :: "r"(mb), "r"(0) : "memory");

    const int kb = b * KPAD;
    const size_t oh = ((size_t)b * CPAIRS + c2) * KPAD;
    #pragma unroll
    for (int q = 0; q < 2; q++) {
        int k0 = tid * 8 + q * 4;
        unsigned h[4], l[4];
        #pragma unroll
        for (int j = 0; j < 4; j++) {
            int a = g_addr[kb + k0 + j];
            float v0 = 0.0f, v1 = 0.0f;
            if (a >= 0) {
                v0 = fminf(fmaxf(sp[a], 0.0f), 6.0f);
                v1 = fminf(fmaxf(sp[HWSZ + a], 0.0f), 6.0f);
            }
            h[j] = pack_split_hi(v0, v1);
            l[j] = pack_split_lo(v0, v1);
        }
        *(uint4*)&g_nfh[oh + k0] = make_uint4(h[0], h[1], h[2], h[3]);
        *(uint4*)&g_nfl[oh + k0] = make_uint4(l[0], l[1], l[2], l[3]);
    }
}

// ---------------- MMA / ldmatrix helpers ----------------
#define MMA_F16(acc, a0, a1, a2, a3, b0, b1)                                    \
    asm volatile(                                                               \
        "mma.sync.aligned.m16n8k16.row.col.f32.f16.f16.f32 "                    \
        "{%0,%1,%2,%3}, {%4,%5,%6,%7}, {%8,%9}, {%0,%1,%2,%3};"                 \
        : "+f"(acc[0]), "+f"(acc[1]), "+f"(acc[2]), "+f"(acc[3])                \
        : "r"(a0), "r"(a1), "r"(a2), "r"(a3), "r"(b0), "r"(b1))

// fp16-accumulator MMA for the small cross terms (2 packed-half2 acc regs)
#define MMA_H16(accp, a0, a1, a2, a3, b0, b1)                                   \
    asm volatile(                                                               \
        "mma.sync.aligned.m16n8k16.row.col.f16.f16.f16.f16 "                    \
        "{%0,%1}, {%2,%3,%4,%5}, {%6,%7}, {%0,%1};"                             \
        : "+r"(accp[0]), "+r"(accp[1])                                          \
        : "r"(a0), "r"(a1), "r"(a2), "r"(a3), "r"(b0), "r"(b1))

#define LDSM_X4(r0, r1, r2, r3, addr)                                           \
    asm volatile("ldmatrix.sync.aligned.m8n8.x4.shared.b16 {%0,%1,%2,%3}, [%4];"\
        : "=r"(r0), "=r"(r1), "=r"(r2), "=r"(r3) : "r"(addr))

__device__ __forceinline__ void add_cross(float* acc, const unsigned* accp) {
    __half2 h0 = *reinterpret_cast<const __half2*>(&accp[0]);
    __half2 h1 = *reinterpret_cast<const __half2*>(&accp[1]);
    acc[0] += __low2float(h0);  acc[1] += __high2float(h0);
    acc[2] += __low2float(h1);  acc[3] += __high2float(h1);
}

// ---------------- gemm1: g1 = nf @ w1 — cp.async 3-stage, split accumulators ----------------
extern "C" __global__ __launch_bounds__(256, 2)
void gemm1_kernel() {
    extern __shared__ unsigned dsm[];
    const int tid  = threadIdx.x;
    const int lane = tid & 31;
    const int warp = tid >> 5;
    const int wm = (warp & 1) * 32;
    const int wn = (warp >> 1) * 32;
    const int b = blockIdx.x >> 5;
    const int t = blockIdx.x & 31;

    const int ac2 = tid >> 4;
    const int am4 = (tid & 15) * 4;
    const int bn  = tid >> 1;
    const int bk8 = (tid & 1) * 8;

    const size_t abase = (size_t)b * CPAIRS * KPAD + t * 64;
    const uint32_t sbase = s2u(dsm);

    float    acc[2][4][4];
    unsigned accp[2][4][2];
    #pragma unroll
    for (int mt = 0; mt < 2; mt++)
        #pragma unroll
        for (int nt = 0; nt < 4; nt++) {
            #pragma unroll
            for (int q = 0; q < 4; q++) acc[mt][nt][q] = 0.0f;
            accp[mt][nt][0] = 0u; accp[mt][nt][1] = 0u;
        }

    int aw[2];
    #pragma unroll
    for (int mt = 0; mt < 2; mt++)
        aw[mt] = (lane & 3) * ST_A + wm + mt * 16 + (lane >> 2);

    uint32_t bA0[2];
    #pragma unroll
    for (int p = 0; p < 2; p++) {
        int row = wn + p * 16 + ((lane >> 4) << 3) + (lane & 7);
        int col = ((lane >> 3) & 1) * 4;
        bA0[p] = sbase + (uint32_t)(G1_BH + row * SST + col) * 4;
    }

    auto issue_stage = [&](int kt, int stg) {
        const uint32_t sw = sbase + (uint32_t)(stg * G1_STGW) * 4;
        const size_t ga = abase + (size_t)(kt * 16 + ac2) * KPAD + am4;
        CP16(sw + (uint32_t)(G1_AH + ac2 * ST_A + am4) * 4, &g_nfh[ga]);
        CP16(sw + (uint32_t)(G1_AL + ac2 * ST_A + am4) * 4, &g_nfl[ga]);
        const int gb = bn * (CH / 2) + kt * 16 + bk8;
        CP16(sw + (uint32_t)(G1_BH + bn * SST + bk8) * 4,     &g_w1h[gb]);
        CP16(sw + (uint32_t)(G1_BH + bn * SST + bk8 + 4) * 4, &g_w1h[gb + 4]);
        CP16(sw + (uint32_t)(G1_BL + bn * SST + bk8) * 4,     &g_w1l[gb]);
        CP16(sw + (uint32_t)(G1_BL + bn * SST + bk8 + 4) * 4, &g_w1l[gb + 4]);
        asm volatile("cp.async.commit_group;" ::: "memory");
    };

    issue_stage(0, 0);
    issue_stage(1, 1);
    issue_stage(2, 2);

    for (int kt = 0; kt < 16; kt++) {
        const int stg = kt % 3;
        if (kt < 14)       asm volatile("cp.async.wait_group 2;" ::: "memory");
        else if (kt == 14) asm volatile("cp.async.wait_group 1;" ::: "memory");
        else               asm volatile("cp.async.wait_group 0;" ::: "memory");
        __syncthreads();

        const int sbw = stg * G1_STGW;
        const uint32_t sbb = (uint32_t)(stg * G1_STGW) * 4;

        #pragma unroll
        for (int ks = 0; ks < 2; ks++) {
            const int ko = ks * 8 * ST_A;
            unsigned aH[2][4], aL[2][4], bHf[4][2], bLf[4][2];
            #pragma unroll
            for (int mt = 0; mt < 2; mt++) {
                int base = sbw + aw[mt] + ko;
                aH[mt][0] = dsm[base];
                aH[mt][1] = dsm[base + 8];
                aH[mt][2] = dsm[base + 4 * ST_A];
                aH[mt][3] = dsm[base + 4 * ST_A + 8];
                aL[mt][0] = dsm[base + G1_AL];
                aL[mt][1] = dsm[base + G1_AL + 8];
                aL[mt][2] = dsm[base + G1_AL + 4 * ST_A];
                aL[mt][3] = dsm[base + G1_AL + 4 * ST_A + 8];
            }
            #pragma unroll
            for (int p = 0; p < 2; p++) {
                LDSM_X4(bHf[2*p][0], bHf[2*p][1], bHf[2*p+1][0], bHf[2*p+1][1],
                        bA0[p] + sbb + ks * 32);
                LDSM_X4(bLf[2*p][0], bLf[2*p][1], bLf[2*p+1][0], bLf[2*p+1][1],
                        bA0[p] + sbb + ks * 32 + (uint32_t)(G1_BL - G1_BH) * 4);
            }
            #pragma unroll
            for (int mt = 0; mt < 2; mt++)
                #pragma unroll
                for (int nt = 0; nt < 4; nt++) {
                    MMA_H16(accp[mt][nt], aL[mt][0], aL[mt][1], aL[mt][2], aL[mt][3],
                            bHf[nt][0], bHf[nt][1]);
                    MMA_H16(accp[mt][nt], aH[mt][0], aH[mt][1], aH[mt][2], aH[mt][3],
                            bLf[nt][0], bLf[nt][1]);
                    MMA_F16(acc[mt][nt], aH[mt][0], aH[mt][1], aH[mt][2], aH[mt][3],
                            bHf[nt][0], bHf[nt][1]);
                }
        }
        __syncthreads();
        if (kt + 3 < 16) issue_stage(kt + 3, stg);
    }

    #pragma unroll
    for (int mt = 0; mt < 2; mt++) {
        int rk = t * 64 + wm + mt * 16 + (lane >> 2);
        int colb = (lane & 3) * 2;
        #pragma unroll
        for (int nt = 0; nt < 4; nt++) {
            add_cross(acc[mt][nt], accp[mt][nt]);
            int col = wn + nt * 8 + colb;
            if (rk < KSEL)
                *(float2*)&g_g1[(size_t)(b * KSEL + rk) * ND + col] =
                    make_float2(acc[mt][nt][0], acc[mt][nt][1]);
            if (rk + 8 < KSEL)
                *(float2*)&g_g1[(size_t)(b * KSEL + rk + 8) * ND + col] =
                    make_float2(acc[mt][nt][2], acc[mt][nt][3]);
        }
    }
}

// ---------------- gemm2: g2 = x1 @ w2 (split accumulators) ----------------
struct GemmSmem {
    unsigned AsH[64 * SST], AsL[64 * SST];
    unsigned BsH[128 * SST], BsL[128 * SST];
};

extern "C" __global__ __launch_bounds__(256, 2)
void gemm2_kernel() {
    __shared__ GemmSmem S;
    const int tid  = threadIdx.x;
    const int lane = tid & 31;
    const int warp = tid >> 5;
    const int wm = (warp & 1) * 32;
    const int wn = (warp >> 1) * 32;
    const int gm = blockIdx.x * 64;
    const int K2 = ND / 2;

    const int arow = tid >> 2, aq = tid & 3;
    const int brow = tid >> 1, bkb = (tid & 1) * 8;

    float    acc[2][4][4];
    unsigned accp[2][4][2];
    #pragma unroll
    for (int mt = 0; mt < 2; mt++)
        #pragma unroll
        for (int nt = 0; nt < 4; nt++) {
            #pragma unroll
            for (int q = 0; q < 4; q++) acc[mt][nt][q] = 0.0f;
            accp[mt][nt][0] = 0u; accp[mt][nt][1] = 0u;
        }

    uint32_t aAH[2], aAL[2], bAH[2], bAL[2];
    #pragma unroll
    for (int mt = 0; mt < 2; mt++) {
        int row = wm + mt * 16 + (lane & 15);
        int col = (lane >> 4) << 2;
        aAH[mt] = s2u(&S.AsH[row * SST + col]);
        aAL[mt] = s2u(&S.AsL[row * SST + col]);
    }
    #pragma unroll
    for (int p = 0; p < 2; p++) {
        int row = wn + p * 16 + ((lane >> 4) << 3) + (lane & 7);
        int col = ((lane >> 3) & 1) * 4;
        bAH[p] = s2u(&S.BsH[row * SST + col]);
        bAL[p] = s2u(&S.BsL[row * SST + col]);
    }

    float v[8];
    uint4 bh[2], bl[2];
    {
        #pragma unroll
        for (int q = 0; q < 2; q++) {
            float4 tv = *(const float4*)&g_x1[(size_t)(gm + arow) * ND + aq * 8 + q * 4];
            v[q * 4] = tv.x; v[q * 4 + 1] = tv.y; v[q * 4 + 2] = tv.z; v[q * 4 + 3] = tv.w;
        }
        bh[0] = *(const uint4*)&g_w2h[brow * K2 + bkb];
        bh[1] = *(const uint4*)&g_w2h[brow * K2 + bkb + 4];
        bl[0] = *(const uint4*)&g_w2l[brow * K2 + bkb];
        bl[1] = *(const uint4*)&g_w2l[brow * K2 + bkb + 4];
    }

    for (int kt = 0; kt < 4; kt++) {
        __syncthreads();
        #pragma unroll
        for (int j = 0; j < 4; j++) {
            int kidx = arow * SST + aq * 4 + j;
            S.AsH[kidx] = pack_split_hi(v[2 * j], v[2 * j + 1]);
            S.AsL[kidx] = pack_split_lo(v[2 * j], v[2 * j + 1]);
        }
        {
            int base = brow * SST + bkb;
            S.BsH[base + 0] = bh[0].x; S.BsH[base + 1] = bh[0].y;
            S.BsH[base + 2] = bh[0].z; S.BsH[base + 3] = bh[0].w;
            S.BsH[base + 4] = bh[1].x; S.BsH[base + 5] = bh[1].y;
            S.BsH[base + 6] = bh[1].z; S.BsH[base + 7] = bh[1].w;
            S.BsL[base + 0] = bl[0].x; S.BsL[base + 1] = bl[0].y;
            S.BsL[base + 2] = bl[0].z; S.BsL[base + 3] = bl[0].w;
            S.BsL[base + 4] = bl[1].x; S.BsL[base + 5] = bl[1].y;
            S.BsL[base + 6] = bl[1].z; S.BsL[base + 7] = bl[1].w;
        }
        __syncthreads();

        if (kt + 1 < 4) {
            int cb = (kt + 1) * 32 + aq * 8;
            #pragma unroll
            for (int q = 0; q < 2; q++) {
                float4 tv = *(const float4*)&g_x1[(size_t)(gm + arow) * ND + cb + q * 4];
                v[q * 4] = tv.x; v[q * 4 + 1] = tv.y; v[q * 4 + 2] = tv.z; v[q * 4 + 3] = tv.w;
            }
            int k2n = (kt + 1) * 16;
            bh[0] = *(const uint4*)&g_w2h[brow * K2 + k2n + bkb];
            bh[1] = *(const uint4*)&g_w2h[brow * K2 + k2n + bkb + 4];
            bl[0] = *(const uint4*)&g_w2l[brow * K2 + k2n + bkb];
            bl[1] = *(const uint4*)&g_w2l[brow * K2 + k2n + bkb + 4];
        }

        #pragma unroll
        for (int ks = 0; ks < 2; ks++) {
            const uint32_t off = ks * 32;
            unsigned aH[2][4], aL[2][4], bHf[4][2], bLf[4][2];
            #pragma unroll
            for (int mt = 0; mt < 2; mt++) {
                LDSM_X4(aH[mt][0], aH[mt][1], aH[mt][2], aH[mt][3], aAH[mt] + off);
                LDSM_X4(aL[mt][0], aL[mt][1], aL[mt][2], aL[mt][3], aAL[mt] + off);
            }
            #pragma unroll
            for (int p = 0; p < 2; p++) {
                LDSM_X4(bHf[2*p][0], bHf[2*p][1], bHf[2*p+1][0], bHf[2*p+1][1], bAH[p] + off);
                LDSM_X4(bLf[2*p][0], bLf[2*p][1], bLf[2*p+1][0], bLf[2*p+1][1], bAL[p] + off);
            }
            #pragma unroll
            for (int mt = 0; mt < 2; mt++)
                #pragma unroll
                for (int nt = 0; nt < 4; nt++) {
                    MMA_H16(accp[mt][nt], aL[mt][0], aL[mt][1], aL[mt][2], aL[mt][3],
                            bHf[nt][0], bHf[nt][1]);
                    MMA_H16(accp[mt][nt], aH[mt][0], aH[mt][1], aH[mt][2], aH[mt][3],
                            bLf[nt][0], bLf[nt][1]);
                    MMA_F16(acc[mt][nt], aH[mt][0], aH[mt][1], aH[mt][2], aH[mt][3],
                            bHf[nt][0], bHf[nt][1]);
                }
        }
    }

    #pragma unroll
    for (int mt = 0; mt < 2; mt++) {
        int row0 = gm + wm + mt * 16 + (lane >> 2);
        int colb = (lane & 3) * 2;
        #pragma unroll
        for (int nt = 0; nt < 4; nt++) {
            add_cross(acc[mt][nt], accp[mt][nt]);
            int col = wn + nt * 8 + colb;
            *(float2*)&g_g2[(size_t)row0 * ND + col] =
                make_float2(acc[mt][nt][0], acc[mt][nt][1]);
            *(float2*)&g_g2[(size_t)(row0 + 8) * ND + col] =
                make_float2(acc[mt][nt][2], acc[mt][nt][3]);
        }
    }
}

// ---------------- sparse 3x3 neighbor sums ----------------
extern "C" __global__ __launch_bounds__(256)
void nsum1_kernel(const float* __restrict__ b1) {
    const int row = blockIdx.x * 8 + (threadIdx.x >> 5);
    const int lane = threadIdx.x & 31;
    const int b = row / KSEL, k = row - b * KSEL;
    const int i = g_sorted_idx[row];
    const int py = i / WW, px = i % WW;
    int nb = -1;
    if (lane < 9) {
        int ny = py + lane / 3 - 1, nx = px + lane % 3 - 1;
        if ((unsigned)ny < HH && (unsigned)nx < WW)
            nb = g_pos[b * HWSZ + ny * WW + nx];
    }
    float4 acc = *(const float4*)&b1[(size_t)k * ND + lane * 4];
    #pragma unroll
    for (int j = 0; j < 9; j++) {
        int n = __shfl_sync(0xFFFFFFFFu, nb, j);
        if (n >= 0) {
            float4 v = *(const float4*)&g_g1[(size_t)(b * KSEL + n) * ND + lane * 4];
            acc.x += v.x; acc.y += v.y; acc.z += v.z; acc.w += v.w;
        }
    }
    *(float4*)&g_x1[(size_t)row * ND + lane * 4] = acc;
}

extern "C" __global__ __launch_bounds__(256)
void final_kernel(const float* __restrict__ b2, float* __restrict__ out) {
    const int row = blockIdx.x * 8 + (threadIdx.x >> 5);
    const int lane = threadIdx.x & 31;
    const int b = row / KSEL, k = row - b * KSEL;
    const int i = g_sorted_idx[row];
    const int py = i / WW, px = i % WW;
    int nb = -1;
    if (lane < 9) {
        int ny = py + lane / 3 - 1, nx = px + lane % 3 - 1;
        if ((unsigned)ny < HH && (unsigned)nx < WW)
            nb = g_pos[b * HWSZ + ny * WW + nx];
    }
    float4 acc = *(const float4*)&b2[(size_t)k * ND + lane * 4];
    float4 x1v = *(const float4*)&g_x1[(size_t)row * ND + lane * 4];
    acc.x += x1v.x; acc.y += x1v.y; acc.z += x1v.z; acc.w += x1v.w;
    #pragma unroll
    for (int j = 0; j < 9; j++) {
        int n = __shfl_sync(0xFFFFFFFFu, nb, j);
        if (n >= 0) {
            float4 v = *(const float4*)&g_g2[(size_t)(b * KSEL + n) * ND + lane * 4];
            acc.x += v.x; acc.y += v.y; acc.z += v.z; acc.w += v.w;
        }
    }
    float4 o = make_float4(tanhf(acc.x), tanhf(acc.y), tanhf(acc.z), tanhf(acc.w));
    *(float4*)&out[(size_t)row * ND + lane * 4] = o;
}

// ---------------- launch ----------------
extern "C" void kernel_launch(void* const* d_in, const int* in_sizes, int n_in,
                              void* d_out, int out_size) {
    const float* feat = (const float*)d_in[0];
    const float* pred = (const float*)d_in[1];
    const float* w1   = (const float*)d_in[2];
    const float* b1   = (const float*)d_in[3];
    const float* w2   = (const float*)d_in[4];
    const float* b2   = (const float*)d_in[5];
    float* out = (float*)d_out;

    const int feat_elems = NROWS * ND;
    const int write_idx = (out_size >= feat_elems + NROWS) ? 1 : 0;

    cudaFuncSetAttribute((const void*)gather_kernel,
                         cudaFuncAttributeMaxDynamicSharedMemorySize, 60000);
    cudaFuncSetAttribute((const void*)gemm1_kernel,
                         cudaFuncAttributeMaxDynamicSharedMemorySize, G1_SMEM);

    prep_kernel<<<(ND * (CH / 2) + ND * (ND / 2) + 255) / 256, 256>>>(w1, w2);
    topk_kernel<<<NB, 1024>>>(pred, out, write_idx);
    gather_kernel<<<NB * CPAIRS, 256, 60000>>>(feat);
    gemm1_kernel<<<NB * 32, 256, G1_SMEM>>>();
    nsum1_kernel<<<NROWS / 8, 256>>>(b1);
    gemm2_kernel<<<NROWS / 64, 256>>>();
    final_kernel<<<NROWS / 8, 256>>>(b2, out);
}